// round 14
// baseline (speedup 1.0000x reference)
#include <cuda_runtime.h>

// Fixed shapes from setup_inputs
#define LQ 512   // sequence length
#define DD 256   // per-tensor feature dim
#define FD 512   // 2*DD (MLP hidden)
#define NB 2     // batch
#define NH 8     // heads
#define DK 64    // head dim

// Scratch (no cudaMalloc allowed)
__device__ float g_A[NB * LQ * FD];   // d1 @ W1[:DD]
__device__ float g_C[NB * LQ * FD];   // d0 @ W1[DD:] + b1
__device__ float g_D[NB * LQ * LQ];   // decisions: 0 or -1e9

typedef unsigned long long u64;

#define FFMA2(d,a,b,c) asm("fma.rn.f32x2 %0,%1,%2,%3;" : "=l"(d) : "l"(a),"l"(b),"l"(c))
#define FADD2(d,a,b)   asm("add.rn.f32x2 %0,%1,%2;"    : "=l"(d) : "l"(a),"l"(b))

__device__ __forceinline__ float2 unpk(u64 p) {
    float lo, hi;
    asm("mov.b64 {%0,%1},%2;" : "=f"(lo), "=f"(hi) : "l"(p));
    return make_float2(lo, hi);
}
__device__ __forceinline__ u64 pk(float lo, float hi) {
    u64 d;
    asm("mov.b64 %0,{%1,%2};" : "=l"(d) : "f"(lo), "f"(hi));
    return d;
}

#define ABS2_MASK 0x7FFFFFFF7FFFFFFFULL   // |x| on both packed halves
#define EIGHTH2   0x3E0000003E000000ULL   // {0.125f, 0.125f}

// ---------------------------------------------------------------------------
// Kernel 1: A = d1 @ W1_top, C = d0 @ W1_bot + b1  — R1/R13 VERBATIM (24.4us).
// ---------------------------------------------------------------------------
__global__ __launch_bounds__(256) void gemm_ac_kernel(
    const float* __restrict__ d1, const float* __restrict__ d0,
    const float* __restrict__ W1, const float* __restrict__ b1)
{
    const int z = blockIdx.z;                       // 0 -> A, 1 -> C
    const float* src = z ? d0 : d1;                 // [1024, 256]
    const float* W   = W1 + (z ? (size_t)DD * FD : 0);  // [256, 512]
    float* dst = z ? g_C : g_A;

    __shared__ float As[64][33];   // [m][k], pad breaks stride-128 bank repeat
    __shared__ float Bs[32][64];   // [k][n]

    const int m0 = blockIdx.y * 64;
    const int n0 = blockIdx.x * 64;
    const int t  = threadIdx.x;
    const int tx = t & 15, ty = t >> 4;

    float acc[4][4] = {};

    for (int k0 = 0; k0 < DD; k0 += 32) {
        #pragma unroll
        for (int r = 0; r < 8; r++) {
            int lin = t + r * 256;
            int mm = lin >> 5, kk = lin & 31;
            As[mm][kk] = src[(size_t)(m0 + mm) * DD + k0 + kk];
        }
        #pragma unroll
        for (int r = 0; r < 8; r++) {
            int lin = t + r * 256;
            int kk = lin >> 6, nn = lin & 63;
            Bs[kk][nn] = W[(size_t)(k0 + kk) * FD + n0 + nn];
        }
        __syncthreads();

        #pragma unroll
        for (int kk = 0; kk < 32; kk++) {
            float a[4], b[4];
            #pragma unroll
            for (int i = 0; i < 4; i++) a[i] = As[ty * 4 + i][kk];
            #pragma unroll
            for (int j = 0; j < 4; j++) b[j] = Bs[kk][tx * 4 + j];
            #pragma unroll
            for (int i = 0; i < 4; i++)
                #pragma unroll
                for (int j = 0; j < 4; j++)
                    acc[i][j] = fmaf(a[i], b[j], acc[i][j]);
        }
        __syncthreads();
    }

    #pragma unroll
    for (int i = 0; i < 4; i++) {
        int m = m0 + ty * 4 + i;
        #pragma unroll
        for (int j = 0; j < 4; j++) {
            int n = n0 + tx * 4 + j;
            float v = acc[i][j];
            if (z) v += b1[n];          // fold b1 into C
            dst[(size_t)m * FD + n] = v;
        }
    }
}

// ---------------------------------------------------------------------------
// Kernel 2: decisions[b,i,j] = (sum_f relu(A[b,i,f]+C[b,j,f])*w2d[f] + b2d > 0)
//           ? -1e9 : 0
// CHANGED vs R13: tile 32i x 64j (was 64x64) -> grid 8x16x2 = 256 blocks
// (was 128 on 148 SMs). Per-thread 2i x 4j (4 u64 accs). Everything else
// identical: j-packed math, exact relu identity relu(s)*w = (s+|s|)*(w/2),
// f-chunk 32 with chunk-local partials (per-output summation order is
// bit-identical to R1/R13 — precision-critical).
// ---------------------------------------------------------------------------
__global__ __launch_bounds__(256) void decisions_kernel(
    const float* __restrict__ W2, const float* __restrict__ b2)
{
    const int b  = blockIdx.z;
    const int i0 = blockIdx.y * 32;
    const int j0 = blockIdx.x * 64;
    const float* Ab = g_A + (size_t)b * LQ * FD;
    const float* Cb = g_C + (size_t)b * LQ * FD;

    __shared__ float As[32][33];                    // [i][f]
    __shared__ __align__(16) float Cs_T[32][68];    // [f][j] transposed, pad 68
    __shared__ __align__(16) float2 ws2[FD];        // {w/2, w/2}

    const int t  = threadIdx.x;
    const int tx = t & 15, ty = t >> 4;

    for (int f = t; f < FD; f += 256) {
        float w = 0.5f * (W2[2 * f + 1] - W2[2 * f]);
        ws2[f] = make_float2(w, w);
    }

    u64 acc[2][2] = {};

    for (int f0 = 0; f0 < FD; f0 += 32) {
        __syncthreads();
        #pragma unroll
        for (int r = 0; r < 4; r++) {               // A: 32i x 32f = 1024
            int lin = t + r * 256;
            int mm = lin >> 5, ff = lin & 31;
            As[mm][ff] = Ab[(size_t)(i0 + mm) * FD + f0 + ff];
        }
        #pragma unroll
        for (int r = 0; r < 8; r++) {               // C: 64j x 32f = 2048
            int lin = t + r * 256;
            int jj = lin >> 5, ff = lin & 31;
            Cs_T[ff][jj] = Cb[(size_t)(j0 + jj) * FD + f0 + ff];
        }
        __syncthreads();

        u64 accC[2][2] = {};
        #pragma unroll
        for (int ff = 0; ff < 32; ff++) {
            u64 wd = *(const u64*)&ws2[f0 + ff];
            u64 c0 = *(const u64*)&Cs_T[ff][tx * 4];
            u64 c1 = *(const u64*)&Cs_T[ff][tx * 4 + 2];
            #pragma unroll
            for (int i = 0; i < 2; i++) {
                float av = As[ty * 2 + i][ff];
                u64 ad = pk(av, av);
                u64 s, s2;
                FADD2(s, ad, c0);
                s2 = s & ABS2_MASK;                 // |s|
                FADD2(s2, s, s2);                   // 2*relu(s), exact
                FFMA2(accC[i][0], s2, wd, accC[i][0]);   // *(w/2): exact product
                FADD2(s, ad, c1);
                s2 = s & ABS2_MASK;
                FADD2(s2, s, s2);
                FFMA2(accC[i][1], s2, wd, accC[i][1]);
            }
        }
        #pragma unroll
        for (int i = 0; i < 2; i++) {
            FADD2(acc[i][0], acc[i][0], accC[i][0]);
            FADD2(acc[i][1], acc[i][1], accC[i][1]);
        }
    }

    const float b2d = b2[1] - b2[0];
    float* Db = g_D + (size_t)b * LQ * LQ;
    #pragma unroll
    for (int i = 0; i < 2; i++) {
        float2 p0 = unpk(acc[i][0]), p1 = unpk(acc[i][1]);
        int ii = i0 + ty * 2 + i;
        float4 r = make_float4(
            (p0.x + b2d > 0.f) ? -1e9f : 0.f, (p0.y + b2d > 0.f) ? -1e9f : 0.f,
            (p1.x + b2d > 0.f) ? -1e9f : 0.f, (p1.y + b2d > 0.f) ? -1e9f : 0.f);
        *(float4*)&Db[(size_t)ii * LQ + j0 + tx * 4] = r;
    }
}

// ---------------------------------------------------------------------------
// Kernel 3: out[b,n,i,j] = dot(q[b,n,i,:], k[b,n,j,:]) / 8 + D[b,i,j]
// R13 VERBATIM (j-packed, 64x64, 1024 blocks).
// ---------------------------------------------------------------------------
__global__ __launch_bounds__(256) void attn_kernel(
    const float* __restrict__ q, const float* __restrict__ k,
    float* __restrict__ out)
{
    const int bn = blockIdx.z;          // 0..15 = b*NH + n
    const int b  = bn >> 3;
    const int i0 = blockIdx.y * 64;
    const int j0 = blockIdx.x * 64;
    const float* Q = q + (size_t)bn * LQ * DK;
    const float* K = k + (size_t)bn * LQ * DK;

    __shared__ float Qs[64][65];                    // [i][d]
    __shared__ __align__(16) float Ks_T[64][68];    // [d][j] transposed

    const int t  = threadIdx.x;
    const int tx = t & 15, ty = t >> 4;

    #pragma unroll
    for (int r = 0; r < 16; r++) {
        int lin = t + r * 256;
        int ii = lin >> 6, dd = lin & 63;
        Qs[ii][dd] = Q[(size_t)(i0 + ii) * DK + dd];
        Ks_T[dd][ii] = K[(size_t)(j0 + ii) * DK + dd];
    }
    __syncthreads();

    u64 acc[4][2] = {};
    #pragma unroll 16
    for (int dd = 0; dd < DK; dd++) {
        u64 c0 = *(const u64*)&Ks_T[dd][tx * 4];
        u64 c1 = *(const u64*)&Ks_T[dd][tx * 4 + 2];
        #pragma unroll
        for (int i = 0; i < 4; i++) {
            float av = Qs[ty * 4 + i][dd];
            u64 ad = pk(av, av);
            FFMA2(acc[i][0], ad, c0, acc[i][0]);
            FFMA2(acc[i][1], ad, c1, acc[i][1]);
        }
    }

    const float* Db = g_D + (size_t)b * LQ * LQ;
    float* O = out + (size_t)bn * LQ * LQ;
    const u64 e2 = EIGHTH2;
    #pragma unroll
    for (int i = 0; i < 4; i++) {
        int row = i0 + ty * 4 + i;
        ulonglong2 dv = *(const ulonglong2*)&Db[(size_t)row * LQ + j0 + tx * 4];
        ulonglong2 r;
        FFMA2(r.x, acc[i][0], e2, dv.x);            // qk*0.125 + D, packed
        FFMA2(r.y, acc[i][1], e2, dv.y);
        *(ulonglong2*)&O[(size_t)row * LQ + j0 + tx * 4] = r;
    }
}

// ---------------------------------------------------------------------------
// Inputs (metadata order): q, k, d0, d1, W1, b1, W2, b2
// ---------------------------------------------------------------------------
extern "C" void kernel_launch(void* const* d_in, const int* in_sizes, int n_in,
                              void* d_out, int out_size)
{
    const float* q  = (const float*)d_in[0];   // [2,8,512,64]
    const float* k  = (const float*)d_in[1];   // [2,8,512,64]
    const float* d0 = (const float*)d_in[2];   // [2,512,256]
    const float* d1 = (const float*)d_in[3];   // [2,512,256]
    const float* W1 = (const float*)d_in[4];   // [512,512]
    const float* b1 = (const float*)d_in[5];   // [512]
    const float* W2 = (const float*)d_in[6];   // [512,2]
    const float* b2 = (const float*)d_in[7];   // [2]
    float* out = (float*)d_out;                // [2,8,512,512]

    (void)in_sizes; (void)n_in; (void)out_size;

    gemm_ac_kernel  <<<dim3(FD / 64, (NB * LQ) / 64, 2),   256>>>(d1, d0, W1, b1);
    decisions_kernel<<<dim3(LQ / 64, LQ / 32, NB),         256>>>(W2, b2);
    attn_kernel     <<<dim3(LQ / 64, LQ / 64, NB * NH),    256>>>(q, k, out);
}